// round 13
// baseline (speedup 1.0000x reference)
#include <cuda_runtime.h>
#include <cuda_fp16.h>
#include <cstdint>

#define N1C 40000
#define N2C 8000
#define E1C 1000000
#define E2C 200000
#define DIN 256
#define HID 256
#define NXROWS 200000

// ---------------- scratch (device globals: no allocation allowed) ----------
__device__ __align__(16) __half g_xh[(size_t)NXROWS * DIN];   // fp16 copy of x (102MB)
__device__ __align__(16) __half g_h1[(size_t)N1C * HID];      // layer-1 output, fp16
__device__ __align__(16) __half g_A[(size_t)N1C * DIN];       // mean part of A only
__device__ __align__(16) __half g_B[2 * 512 * 256];           // fp16 weights
__device__ __align__(16) int g_hist[N1C + N2C];               // zero-init; scan re-zeros
__device__ int g_done;                                        // last-block counter (self-resetting)
__device__ int g_off1[N1C + 1];
__device__ int g_cur1[N1C];
__device__ int g_off2[N2C + 1];
__device__ int g_cur2[N2C];
__device__ int g_ss1[E1C];
__device__ int g_ss2[E2C];

// ---------------- helpers ----------------------------------------------------
__device__ __forceinline__ uint32_t smem_u32(const void* p) {
    uint32_t a;
    asm("{ .reg .u64 t; cvta.to.shared.u64 t, %1; cvt.u32.u64 %0, t; }" : "=r"(a) : "l"(p));
    return a;
}
__device__ __forceinline__ void cp16p(uint32_t dst, const void* src, bool pred) {
    int n = pred ? 16 : 0;
    asm volatile("cp.async.cg.shared.global [%0], [%1], 16, %2;" :: "r"(dst), "l"(src), "r"(n));
}
#define CP_COMMIT() asm volatile("cp.async.commit_group;" ::: "memory")
__device__ __forceinline__ void ldsm4(uint32_t& r0, uint32_t& r1, uint32_t& r2, uint32_t& r3, uint32_t a) {
    asm volatile("ldmatrix.sync.aligned.m8n8.x4.shared.b16 {%0,%1,%2,%3}, [%4];"
                 : "=r"(r0), "=r"(r1), "=r"(r2), "=r"(r3) : "r"(a));
}
__device__ __forceinline__ void ldsm4t(uint32_t& r0, uint32_t& r1, uint32_t& r2, uint32_t& r3, uint32_t a) {
    asm volatile("ldmatrix.sync.aligned.m8n8.x4.trans.shared.b16 {%0,%1,%2,%3}, [%4];"
                 : "=r"(r0), "=r"(r1), "=r"(r2), "=r"(r3) : "r"(a));
}
__device__ __forceinline__ void mma16816h(float* c, const uint32_t* a, const uint32_t* b) {
    asm volatile("mma.sync.aligned.m16n8k16.row.col.f32.f16.f16.f32 "
                 "{%0,%1,%2,%3}, {%4,%5,%6,%7}, {%8,%9}, {%0,%1,%2,%3};"
                 : "+f"(c[0]), "+f"(c[1]), "+f"(c[2]), "+f"(c[3])
                 : "r"(a[0]), "r"(a[1]), "r"(a[2]), "r"(a[3]), "r"(b[0]), "r"(b[1]));
}
__device__ __forceinline__ uint32_t f2h2(float a, float b) {
    __half2 h = __floats2half2_rn(a, b);
    return *reinterpret_cast<uint32_t*>(&h);
}
__device__ __forceinline__ void addh2(float& a, float& b, uint32_t p) {
    __half2 h = *reinterpret_cast<__half2*>(&p);
    float2 f = __half22float2(h);
    a += f.x; b += f.y;
}

// ---------------- scan helper (1024 threads; L2-coherent reads; re-zeros hist) --
__device__ void scan_dev(int* __restrict__ hist, int n,
                         int* __restrict__ off, int* __restrict__ cur) {
    __shared__ int part[1024];
    __syncthreads();
    int t = threadIdx.x;
    int chunk = (n + 1023) >> 10;
    int b = t * chunk;
    int s = 0;
    for (int i = 0; i < chunk; i++)
        if (b + i < n) s += __ldcg(hist + b + i);
    part[t] = s;
    __syncthreads();
#pragma unroll
    for (int d = 1; d < 1024; d <<= 1) {
        int v = (t >= d) ? part[t - d] : 0;
        __syncthreads();
        part[t] += v;
        __syncthreads();
    }
    int run = (t ? part[t - 1] : 0);
    for (int i = 0; i < chunk; i++) {
        int idx = b + i;
        if (idx < n) {
            int h = __ldcg(hist + idx);
            hist[idx] = 0;
            off[idx] = run; cur[idx] = run; run += h;
        }
    }
    if (t == 1023) off[n] = part[1023];
}

// ---------------- fused front: hist1 | hist2 | B pack | x convert | scans -------
// 1024 threads/block. Last finishing block performs both exclusive scans.
__global__ __launch_bounds__(1024)
void hist_scan_all(const int* __restrict__ dst1, int E1c, int hb1,
                   const int* __restrict__ dst2, int E2c, int hb2,
                   int packBlocks,
                   const float* __restrict__ Wl1, const float* __restrict__ Wr1,
                   const float* __restrict__ Wl2, const float* __restrict__ Wr2,
                   __half* __restrict__ B,
                   const float* __restrict__ x, __half* __restrict__ xh, int nX,
                   int* __restrict__ hist,
                   int* __restrict__ off1, int* __restrict__ cur1,
                   int* __restrict__ off2, int* __restrict__ cur2) {
    int bx = blockIdx.x;
    int tid = threadIdx.x;
    if (bx < hb1 + hb2) {
        const int* dst = (bx < hb1) ? dst1 : dst2;
        int* hh = (bx < hb1) ? hist : hist + N1C;
        int E = (bx < hb1) ? E1c : E2c;
        int lb = (bx < hb1) ? bx : bx - hb1;
        int i = (lb * 1024 + tid) * 4;
        if (i + 4 <= E) {
            int4 d = __ldg(reinterpret_cast<const int4*>(dst + i));
            atomicAdd(hh + d.x, 1);
            atomicAdd(hh + d.y, 1);
            atomicAdd(hh + d.z, 1);
            atomicAdd(hh + d.w, 1);
        } else {
            for (int j = i; j < E; j++) atomicAdd(hh + __ldg(dst + j), 1);
        }
    } else if (bx < hb1 + hb2 + packBlocks) {
        int idx = (bx - hb1 - hb2) * 1024 + tid;  // < 2*512*64
        int l = idx >> 15;
        int k = (idx >> 6) & 511;
        int col = (idx & 63) * 4;
        const float* W = (l == 0) ? ((k < 256) ? Wl1 : Wr1) : ((k < 256) ? Wl2 : Wr2);
        float4 v = __ldg(reinterpret_cast<const float4*>(W + (size_t)(k & 255) * 256 + col));
        size_t o = ((size_t)l * 512 + k) * 256 + col;
        *reinterpret_cast<uint2*>(B + o) = make_uint2(f2h2(v.x, v.y), f2h2(v.z, v.w));
    } else {
        size_t base = ((size_t)(bx - hb1 - hb2 - packBlocks) * 1024 + tid) * 8;
        if (base + 8 <= (size_t)nX) {
            float4 v0 = __ldg(reinterpret_cast<const float4*>(x + base));
            float4 v1 = __ldg(reinterpret_cast<const float4*>(x + base + 4));
            uint4 o;
            o.x = f2h2(v0.x, v0.y); o.y = f2h2(v0.z, v0.w);
            o.z = f2h2(v1.x, v1.y); o.w = f2h2(v1.z, v1.w);
            *reinterpret_cast<uint4*>(xh + base) = o;
        }
    }

    // ---- last-block-done: the final block runs both scans ----
    __shared__ int isLast;
    __threadfence();
    if (tid == 0) {
        int t = atomicAdd(&g_done, 1);
        isLast = (t == (int)gridDim.x - 1) ? 1 : 0;
        if (isLast) g_done = 0;   // reset for next graph replay
    }
    __syncthreads();
    if (isLast) {
        __threadfence();
        scan_dev(hist, N1C, off1, cur1);
        scan_dev(hist + N1C, N2C, off2, cur2);
    }
}

// ---------------- reorder both layers, grid-partitioned -------------------------
__device__ __forceinline__ void reorder_dev(const int* __restrict__ src, const int* __restrict__ dst,
                                            int E, int* __restrict__ cur, int* __restrict__ ssrc,
                                            int lb) {
    int i = (lb * (int)blockDim.x + (int)threadIdx.x) * 4;
    if (i + 4 <= E) {
        int4 d = __ldg(reinterpret_cast<const int4*>(dst + i));
        int4 s = __ldg(reinterpret_cast<const int4*>(src + i));
        int p0 = atomicAdd(cur + d.x, 1);
        int p1 = atomicAdd(cur + d.y, 1);
        int p2 = atomicAdd(cur + d.z, 1);
        int p3 = atomicAdd(cur + d.w, 1);
        ssrc[p0] = s.x; ssrc[p1] = s.y; ssrc[p2] = s.z; ssrc[p3] = s.w;
    } else {
        for (int j = i; j < E; j++) {
            int pos = atomicAdd(cur + __ldg(dst + j), 1);
            ssrc[pos] = __ldg(src + j);
        }
    }
}

__global__ void reorder_all(const int* __restrict__ src1, const int* __restrict__ dst1, int E1c,
                            int* __restrict__ cur1, int* __restrict__ ss1, int rb1,
                            const int* __restrict__ src2, const int* __restrict__ dst2, int E2c,
                            int* __restrict__ cur2, int* __restrict__ ss2) {
    int bx = blockIdx.x;
    if (bx < rb1) reorder_dev(src1, dst1, E1c, cur1, ss1, bx);
    else          reorder_dev(src2, dst2, E2c, cur2, ss2, bx - rb1);
}

// ---------------- segmented gather-mean over fp16 rows -> mean part of A -------
__global__ __launch_bounds__(256)
void agg_mean_h(const __half* __restrict__ xh,
                const int* __restrict__ ssrc, const int* __restrict__ off,
                __half* __restrict__ A, int n_tgt) {
    int w = (blockIdx.x * blockDim.x + threadIdx.x) >> 5;
    if (w >= n_tgt) return;
    int lane = threadIdx.x & 31;
    int s0 = __ldg(off + w), s1 = __ldg(off + w + 1);

    float a0 = 0.f, a1 = 0.f, a2 = 0.f, a3 = 0.f, a4 = 0.f, a5 = 0.f, a6 = 0.f, a7 = 0.f;
    int e = s0;
    for (; e + 8 <= s1; e += 8) {
        int si[8];
#pragma unroll
        for (int j = 0; j < 8; j++) si[j] = __ldg(ssrc + e + j);
        uint4 v[8];
#pragma unroll
        for (int j = 0; j < 8; j++)
            v[j] = __ldg(reinterpret_cast<const uint4*>(xh + (size_t)si[j] * 256) + lane);
#pragma unroll
        for (int j = 0; j < 8; j++) {
            addh2(a0, a1, v[j].x);
            addh2(a2, a3, v[j].y);
            addh2(a4, a5, v[j].z);
            addh2(a6, a7, v[j].w);
        }
    }
    for (; e < s1; e++) {
        int si = __ldg(ssrc + e);
        uint4 v = __ldg(reinterpret_cast<const uint4*>(xh + (size_t)si * 256) + lane);
        addh2(a0, a1, v.x);
        addh2(a2, a3, v.y);
        addh2(a4, a5, v.z);
        addh2(a6, a7, v.w);
    }
    float inv = 1.0f / fmaxf((float)(s1 - s0), 1.0f);
    uint4 om;
    om.x = f2h2(a0 * inv, a1 * inv);
    om.y = f2h2(a2 * inv, a3 * inv);
    om.z = f2h2(a4 * inv, a5 * inv);
    om.w = f2h2(a6 * inv, a7 * inv);

    *(reinterpret_cast<uint4*>(A + (size_t)w * 256) + lane) = om;
}

// ---------------- fp16 GEMM: A = [mean | root(direct)] --------------------------
// chunks 0-3: Am (mean, 256 cols); chunks 4-7: Rt (root rows, read in place).
#define FBM 64
#define FBN 128

template <typename OutT>
__global__ __launch_bounds__(256, 2)
void gemm_fp16(const __half* __restrict__ Am, const __half* __restrict__ Rt,
               const __half* __restrict__ B,
               const float* __restrict__ bias, const float* __restrict__ alpha,
               OutT* __restrict__ out, int M) {
    extern __shared__ char smem[];
    uint32_t sb = smem_u32(smem);
    const uint32_t sA = sb;              // 3 x 8KB
    const uint32_t sB = sb + 24576u;     // 3 x 16KB
    const int tid = threadIdx.x;
    const int wid = tid >> 5, lane = tid & 31;
    const int bm = blockIdx.y * FBM;
    const int bn = blockIdx.x * FBN;
    const int m0 = (wid & 1) * 32;
    const int n0 = (wid >> 1) * 32;

    float acc[2][4][4];
#pragma unroll
    for (int i = 0; i < 2; i++)
#pragma unroll
        for (int j = 0; j < 4; j++)
#pragma unroll
            for (int r = 0; r < 4; r++) acc[i][j][r] = 0.0f;

    const int arow = tid >> 2, aq = tid & 3;
    const bool arok = (bm + arow) < M;

#define LD_AB(c, buf) do { \
        const __half* _sa = ((c) < 4) \
            ? (Am + (size_t)(bm + arow) * 256 + (c) * 64 + aq * 8) \
            : (Rt + (size_t)(bm + arow) * 256 + ((c) - 4) * 64 + aq * 8); \
        uint32_t _da = sA + (uint32_t)(buf) * 8192u; \
        uint32_t _o1 = (((uint32_t)arow * 128u + (uint32_t)aq * 16u) ^ (((uint32_t)arow & 7u) << 4)); \
        uint32_t _o2 = (((uint32_t)arow * 128u + (uint32_t)(aq + 4) * 16u) ^ (((uint32_t)arow & 7u) << 4)); \
        cp16p(_da + _o1, _sa, arok); \
        cp16p(_da + _o2, _sa + 32, arok); \
        const __half* _pb = B + (size_t)((c) * 64) * 256 + bn; \
        uint32_t _db = sB + (uint32_t)(buf) * 16384u; \
        _Pragma("unroll") \
        for (int i = 0; i < 4; i++) { \
            int row = (tid >> 4) + i * 16; \
            int seg = tid & 15; \
            uint32_t off = (((uint32_t)row * 256u + (uint32_t)seg * 16u) ^ (((uint32_t)row & 7u) << 4)); \
            cp16p(_db + off, _pb + (size_t)row * 256 + seg * 8, true); \
        } \
        CP_COMMIT(); \
    } while (0)

    LD_AB(0, 0);
    LD_AB(1, 1);

#pragma unroll
    for (int c = 0; c < 8; c++) {
        const int buf = c % 3;
        if (c + 2 < 8) {
            LD_AB(c + 2, (c + 2) % 3);
            asm volatile("cp.async.wait_group 2;" ::: "memory");
        } else if (c + 1 < 8) {
            asm volatile("cp.async.wait_group 1;" ::: "memory");
        } else {
            asm volatile("cp.async.wait_group 0;" ::: "memory");
        }
        __syncthreads();

        const uint32_t ab = sA + (uint32_t)buf * 8192u;
        const uint32_t bb = sB + (uint32_t)buf * 16384u;
#pragma unroll
        for (int ks = 0; ks < 4; ks++) {
            uint32_t a[2][4];
#pragma unroll
            for (int i = 0; i < 2; i++) {
                uint32_t mrow = (uint32_t)(m0 + i * 16 + (lane & 15));
                uint32_t kb = (uint32_t)(ks * 32 + (lane >> 4) * 16);
                uint32_t off = ((mrow * 128u + kb) ^ ((mrow & 7u) << 4));
                ldsm4(a[i][0], a[i][1], a[i][2], a[i][3], ab + off);
            }
            uint32_t bh[4][2];
#pragma unroll
            for (int j2 = 0; j2 < 2; j2++) {
                uint32_t krow = (uint32_t)(ks * 16 + (lane & 15));
                uint32_t cb = (uint32_t)((n0 + j2 * 16 + (lane >> 4) * 8) * 2);
                uint32_t off = ((krow * 256u + cb) ^ ((krow & 7u) << 4));
                ldsm4t(bh[j2 * 2][0], bh[j2 * 2][1], bh[j2 * 2 + 1][0], bh[j2 * 2 + 1][1], bb + off);
            }
#pragma unroll
            for (int i = 0; i < 2; i++)
#pragma unroll
                for (int j = 0; j < 4; j++)
                    mma16816h(acc[i][j], a[i], bh[j]);
        }
        __syncthreads();
    }

    // ---- epilogue: bias + PReLU + store (fp32 or fp16 out) ----
#pragma unroll
    for (int i = 0; i < 2; i++) {
        int r0 = bm + m0 + i * 16 + (lane >> 2);
#pragma unroll
        for (int j = 0; j < 4; j++) {
            int col = bn + n0 + j * 8 + (lane & 3) * 2;
            float2 bb = __ldg(reinterpret_cast<const float2*>(bias + col));
            float2 aa = __ldg(reinterpret_cast<const float2*>(alpha + col));
#pragma unroll
            for (int h = 0; h < 2; h++) {
                int rr = r0 + h * 8;
                if (rr >= M) continue;
                float v0 = acc[i][j][h * 2 + 0] + bb.x;
                float v1 = acc[i][j][h * 2 + 1] + bb.y;
                v0 = v0 > 0.f ? v0 : aa.x * v0;
                v1 = v1 > 0.f ? v1 : aa.y * v1;
                if (sizeof(OutT) == 4) {
                    *reinterpret_cast<float2*>((float*)out + (size_t)rr * 256 + col) = make_float2(v0, v1);
                } else {
                    uint32_t p = f2h2(v0, v1);
                    *reinterpret_cast<uint32_t*>((__half*)out + (size_t)rr * 256 + col) = p;
                }
            }
        }
    }
#undef LD_AB
}

// ---------------- launch -------------------------------------------------------
extern "C" void kernel_launch(void* const* d_in, const int* in_sizes, int n_in,
                              void* d_out, int out_size) {
    const float* x    = (const float*)d_in[0];
    const int*   src1 = (const int*)d_in[1];
    const int*   dst1 = (const int*)d_in[2];
    const int*   src2 = (const int*)d_in[3];
    const int*   dst2 = (const int*)d_in[4];

    int iW = 5;
    while (iW < n_in && in_sizes[iW] != DIN * HID) iW++;
    const float* W_l1 = (const float*)d_in[iW + 0];
    const float* W_r1 = (const float*)d_in[iW + 1];
    const float* b1   = (const float*)d_in[iW + 2];
    const float* a1   = (const float*)d_in[iW + 3];
    const float* W_l2 = (const float*)d_in[iW + 4];
    const float* W_r2 = (const float*)d_in[iW + 5];
    const float* b2   = (const float*)d_in[iW + 6];
    const float* a2   = (const float*)d_in[iW + 7];

    const int E1 = in_sizes[1];
    const int E2 = in_sizes[3];
    const int nX = in_sizes[0];

    __half *xh, *h1, *A, *B;
    int *hist, *off1, *cur1, *off2, *cur2, *ss1, *ss2;
    cudaGetSymbolAddress((void**)&xh,   g_xh);
    cudaGetSymbolAddress((void**)&h1,   g_h1);
    cudaGetSymbolAddress((void**)&A,    g_A);
    cudaGetSymbolAddress((void**)&B,    g_B);
    cudaGetSymbolAddress((void**)&hist, g_hist);
    cudaGetSymbolAddress((void**)&off1, g_off1);
    cudaGetSymbolAddress((void**)&cur1, g_cur1);
    cudaGetSymbolAddress((void**)&off2, g_off2);
    cudaGetSymbolAddress((void**)&cur2, g_cur2);
    cudaGetSymbolAddress((void**)&ss1,  g_ss1);
    cudaGetSymbolAddress((void**)&ss2,  g_ss2);

    float* out = (float*)d_out;

    const int SMEM_GEMM = 3 * 8192 + 3 * 16384;   // 72KB
    cudaFuncSetAttribute(gemm_fp16<__half>, cudaFuncAttributeMaxDynamicSharedMemorySize, SMEM_GEMM);
    cudaFuncSetAttribute(gemm_fp16<float>,  cudaFuncAttributeMaxDynamicSharedMemorySize, SMEM_GEMM);

    const int hb1 = (E1 + 4095) / 4096;                    // 1024 thr * 4 edges
    const int hb2 = (E2 + 4095) / 4096;
    const int packBlocks = (2 * 512 * 64) / 1024;          // 64
    const int convBlocks = (nX + 1024 * 8 - 1) / (1024 * 8);

    // #1: hist1 | hist2 | B pack | x convert, + fused scans (last block)
    hist_scan_all<<<hb1 + hb2 + packBlocks + convBlocks, 1024>>>(
        dst1, E1, hb1, dst2, E2, hb2, packBlocks,
        W_l1, W_r1, W_l2, W_r2, B, x, xh, nX,
        hist, off1, cur1, off2, cur2);
    // #2: both reorders
    {
        const int rb1 = (E1 + 1023) / 1024;
        const int rb2 = (E2 + 1023) / 1024;
        reorder_all<<<rb1 + rb2, 256>>>(src1, dst1, E1, cur1, ss1, rb1,
                                        src2, dst2, E2, cur2, ss2);
    }
    // #3: layer-1 gather (mean only)
    agg_mean_h<<<(N1C + 7) / 8, 256>>>(xh, ss1, off1, A, N1C);
    // #4: layer-1 GEMM  <-- ncu capture slot
    {
        dim3 grid(HID / FBN, (N1C + FBM - 1) / FBM);
        gemm_fp16<__half><<<grid, 256, SMEM_GEMM>>>(A, xh, B, b1, a1, h1, N1C);
    }
    // #5: layer-2 gather
    agg_mean_h<<<(N2C + 7) / 8, 256>>>(h1, ss2, off2, A, N2C);
    // #6: layer-2 GEMM
    {
        dim3 grid(HID / FBN, (N2C + FBM - 1) / FBM);
        gemm_fp16<float><<<grid, 256, SMEM_GEMM>>>(A, h1, B + 512 * 256, b2, a2, out, N2C);
    }
}

// round 14
// speedup vs baseline: 1.2015x; 1.2015x over previous
#include <cuda_runtime.h>
#include <cuda_fp16.h>
#include <cstdint>

#define N1C 40000
#define N2C 8000
#define E1C 1000000
#define E2C 200000
#define DIN 256
#define HID 256
#define NXROWS 200000

// ---------------- scratch (device globals: no allocation allowed) ----------
__device__ __align__(16) __half g_xh[(size_t)NXROWS * DIN];   // fp16 copy of x (102MB)
__device__ __align__(16) __half g_h1[(size_t)N1C * HID];      // layer-1 output, fp16
__device__ __align__(16) __half g_A[(size_t)N1C * DIN];       // mean part of A only
__device__ __align__(16) __half g_B[2 * 512 * 256];           // fp16 weights
__device__ __align__(16) int g_hist[N1C + N2C];               // zero-init; scan re-zeros
__device__ int g_off1[N1C + 1];
__device__ int g_cur1[N1C];
__device__ int g_off2[N2C + 1];
__device__ int g_cur2[N2C];
__device__ int g_ss1[E1C];
__device__ int g_ss2[E2C];

// ---------------- helpers ----------------------------------------------------
__device__ __forceinline__ uint32_t smem_u32(const void* p) {
    uint32_t a;
    asm("{ .reg .u64 t; cvta.to.shared.u64 t, %1; cvt.u32.u64 %0, t; }" : "=r"(a) : "l"(p));
    return a;
}
__device__ __forceinline__ void cp16p(uint32_t dst, const void* src, bool pred) {
    int n = pred ? 16 : 0;
    asm volatile("cp.async.cg.shared.global [%0], [%1], 16, %2;" :: "r"(dst), "l"(src), "r"(n));
}
#define CP_COMMIT() asm volatile("cp.async.commit_group;" ::: "memory")
__device__ __forceinline__ void ldsm4(uint32_t& r0, uint32_t& r1, uint32_t& r2, uint32_t& r3, uint32_t a) {
    asm volatile("ldmatrix.sync.aligned.m8n8.x4.shared.b16 {%0,%1,%2,%3}, [%4];"
                 : "=r"(r0), "=r"(r1), "=r"(r2), "=r"(r3) : "r"(a));
}
__device__ __forceinline__ void ldsm4t(uint32_t& r0, uint32_t& r1, uint32_t& r2, uint32_t& r3, uint32_t a) {
    asm volatile("ldmatrix.sync.aligned.m8n8.x4.trans.shared.b16 {%0,%1,%2,%3}, [%4];"
                 : "=r"(r0), "=r"(r1), "=r"(r2), "=r"(r3) : "r"(a));
}
__device__ __forceinline__ void mma16816h(float* c, const uint32_t* a, const uint32_t* b) {
    asm volatile("mma.sync.aligned.m16n8k16.row.col.f32.f16.f16.f32 "
                 "{%0,%1,%2,%3}, {%4,%5,%6,%7}, {%8,%9}, {%0,%1,%2,%3};"
                 : "+f"(c[0]), "+f"(c[1]), "+f"(c[2]), "+f"(c[3])
                 : "r"(a[0]), "r"(a[1]), "r"(a[2]), "r"(a[3]), "r"(b[0]), "r"(b[1]));
}
__device__ __forceinline__ uint32_t f2h2(float a, float b) {
    __half2 h = __floats2half2_rn(a, b);
    return *reinterpret_cast<uint32_t*>(&h);
}
__device__ __forceinline__ void addh2(float& a, float& b, uint32_t p) {
    __half2 h = *reinterpret_cast<__half2*>(&p);
    float2 f = __half22float2(h);
    a += f.x; b += f.y;
}

// ---------------- fused front kernel: hist1 | hist2 | B pack | x convert --------
__global__ void hist_all(const int* __restrict__ dst1, int E1c, int* __restrict__ hist1, int hb1,
                         const int* __restrict__ dst2, int E2c, int* __restrict__ hist2, int hb2,
                         int packBlocks,
                         const float* __restrict__ Wl1, const float* __restrict__ Wr1,
                         const float* __restrict__ Wl2, const float* __restrict__ Wr2,
                         __half* __restrict__ B,
                         const float* __restrict__ x, __half* __restrict__ xh, int nX) {
    int bx = blockIdx.x;
    if (bx < hb1 + hb2) {
        const int* dst = (bx < hb1) ? dst1 : dst2;
        int* hist = (bx < hb1) ? hist1 : hist2;
        int E = (bx < hb1) ? E1c : E2c;
        int lb = (bx < hb1) ? bx : bx - hb1;
        int i = (lb * blockDim.x + threadIdx.x) * 4;
        if (i + 4 <= E) {
            int4 d = __ldg(reinterpret_cast<const int4*>(dst + i));
            atomicAdd(hist + d.x, 1);
            atomicAdd(hist + d.y, 1);
            atomicAdd(hist + d.z, 1);
            atomicAdd(hist + d.w, 1);
        } else {
            for (int j = i; j < E; j++) atomicAdd(hist + __ldg(dst + j), 1);
        }
    } else if (bx < hb1 + hb2 + packBlocks) {
        int idx = (bx - hb1 - hb2) * blockDim.x + threadIdx.x;  // < 2*512*64
        int l = idx >> 15;
        int k = (idx >> 6) & 511;
        int col = (idx & 63) * 4;
        const float* W = (l == 0) ? ((k < 256) ? Wl1 : Wr1) : ((k < 256) ? Wl2 : Wr2);
        float4 v = __ldg(reinterpret_cast<const float4*>(W + (size_t)(k & 255) * 256 + col));
        size_t o = ((size_t)l * 512 + k) * 256 + col;
        *reinterpret_cast<uint2*>(B + o) = make_uint2(f2h2(v.x, v.y), f2h2(v.z, v.w));
    } else {
        size_t base = ((size_t)(bx - hb1 - hb2 - packBlocks) * blockDim.x + threadIdx.x) * 8;
        if (base + 8 <= (size_t)nX) {
            float4 v0 = __ldg(reinterpret_cast<const float4*>(x + base));
            float4 v1 = __ldg(reinterpret_cast<const float4*>(x + base + 4));
            uint4 o;
            o.x = f2h2(v0.x, v0.y); o.y = f2h2(v0.z, v0.w);
            o.z = f2h2(v1.x, v1.y); o.w = f2h2(v1.z, v1.w);
            *reinterpret_cast<uint4*>(xh + base) = o;
        }
    }
}

// ---------------- scan both layers in one launch (block 0: L1, block 1: L2) ----
__device__ void scan_dev(int* __restrict__ hist, int n,
                         int* __restrict__ off, int* __restrict__ cur) {
    __shared__ int part[1024];
    int t = threadIdx.x;
    int chunk = (n + 1023) >> 10;
    int b = t * chunk;
    int s = 0;
    for (int i = 0; i < chunk; i++) if (b + i < n) s += hist[b + i];
    part[t] = s;
    __syncthreads();
#pragma unroll
    for (int d = 1; d < 1024; d <<= 1) {
        int v = (t >= d) ? part[t - d] : 0;
        __syncthreads();
        part[t] += v;
        __syncthreads();
    }
    int run = (t ? part[t - 1] : 0);
    for (int i = 0; i < chunk; i++) {
        int idx = b + i;
        if (idx < n) {
            int h = hist[idx];
            hist[idx] = 0;
            off[idx] = run; cur[idx] = run; run += h;
        }
    }
    if (t == 1023) off[n] = part[1023];
}

__global__ void scan_both(int* __restrict__ hist,
                          int* __restrict__ off1, int* __restrict__ cur1,
                          int* __restrict__ off2, int* __restrict__ cur2) {
    if (blockIdx.x == 0) scan_dev(hist, N1C, off1, cur1);
    else                 scan_dev(hist + N1C, N2C, off2, cur2);
}

// ---------------- reorder both layers, grid-partitioned -------------------------
__device__ __forceinline__ void reorder_dev(const int* __restrict__ src, const int* __restrict__ dst,
                                            int E, int* __restrict__ cur, int* __restrict__ ssrc,
                                            int lb) {
    int i = (lb * (int)blockDim.x + (int)threadIdx.x) * 4;
    if (i + 4 <= E) {
        int4 d = __ldg(reinterpret_cast<const int4*>(dst + i));
        int4 s = __ldg(reinterpret_cast<const int4*>(src + i));
        int p0 = atomicAdd(cur + d.x, 1);
        int p1 = atomicAdd(cur + d.y, 1);
        int p2 = atomicAdd(cur + d.z, 1);
        int p3 = atomicAdd(cur + d.w, 1);
        ssrc[p0] = s.x; ssrc[p1] = s.y; ssrc[p2] = s.z; ssrc[p3] = s.w;
    } else {
        for (int j = i; j < E; j++) {
            int pos = atomicAdd(cur + __ldg(dst + j), 1);
            ssrc[pos] = __ldg(src + j);
        }
    }
}

__global__ void reorder_all(const int* __restrict__ src1, const int* __restrict__ dst1, int E1c,
                            int* __restrict__ cur1, int* __restrict__ ss1, int rb1,
                            const int* __restrict__ src2, const int* __restrict__ dst2, int E2c,
                            int* __restrict__ cur2, int* __restrict__ ss2) {
    int bx = blockIdx.x;
    if (bx < rb1) reorder_dev(src1, dst1, E1c, cur1, ss1, bx);
    else          reorder_dev(src2, dst2, E2c, cur2, ss2, bx - rb1);
}

// ---------------- segmented gather-mean over fp16 rows -> mean part of A -------
__global__ __launch_bounds__(256)
void agg_mean_h(const __half* __restrict__ xh,
                const int* __restrict__ ssrc, const int* __restrict__ off,
                __half* __restrict__ A, int n_tgt) {
    int w = (blockIdx.x * blockDim.x + threadIdx.x) >> 5;
    if (w >= n_tgt) return;
    int lane = threadIdx.x & 31;
    int s0 = __ldg(off + w), s1 = __ldg(off + w + 1);

    float a0 = 0.f, a1 = 0.f, a2 = 0.f, a3 = 0.f, a4 = 0.f, a5 = 0.f, a6 = 0.f, a7 = 0.f;
    int e = s0;
    for (; e + 8 <= s1; e += 8) {
        int si[8];
#pragma unroll
        for (int j = 0; j < 8; j++) si[j] = __ldg(ssrc + e + j);
        uint4 v[8];
#pragma unroll
        for (int j = 0; j < 8; j++)
            v[j] = __ldg(reinterpret_cast<const uint4*>(xh + (size_t)si[j] * 256) + lane);
#pragma unroll
        for (int j = 0; j < 8; j++) {
            addh2(a0, a1, v[j].x);
            addh2(a2, a3, v[j].y);
            addh2(a4, a5, v[j].z);
            addh2(a6, a7, v[j].w);
        }
    }
    for (; e < s1; e++) {
        int si = __ldg(ssrc + e);
        uint4 v = __ldg(reinterpret_cast<const uint4*>(xh + (size_t)si * 256) + lane);
        addh2(a0, a1, v.x);
        addh2(a2, a3, v.y);
        addh2(a4, a5, v.z);
        addh2(a6, a7, v.w);
    }
    float inv = 1.0f / fmaxf((float)(s1 - s0), 1.0f);
    uint4 om;
    om.x = f2h2(a0 * inv, a1 * inv);
    om.y = f2h2(a2 * inv, a3 * inv);
    om.z = f2h2(a4 * inv, a5 * inv);
    om.w = f2h2(a6 * inv, a7 * inv);

    *(reinterpret_cast<uint4*>(A + (size_t)w * 256) + lane) = om;
}

// ---------------- fp16 GEMM: A = [mean | root(direct)] --------------------------
#define FBM 64
#define FBN 128

template <typename OutT>
__global__ __launch_bounds__(256, 2)
void gemm_fp16(const __half* __restrict__ Am, const __half* __restrict__ Rt,
               const __half* __restrict__ B,
               const float* __restrict__ bias, const float* __restrict__ alpha,
               OutT* __restrict__ out, int M) {
    extern __shared__ char smem[];
    uint32_t sb = smem_u32(smem);
    const uint32_t sA = sb;              // 3 x 8KB
    const uint32_t sB = sb + 24576u;     // 3 x 16KB
    const int tid = threadIdx.x;
    const int wid = tid >> 5, lane = tid & 31;
    const int bm = blockIdx.y * FBM;
    const int bn = blockIdx.x * FBN;
    const int m0 = (wid & 1) * 32;
    const int n0 = (wid >> 1) * 32;

    float acc[2][4][4];
#pragma unroll
    for (int i = 0; i < 2; i++)
#pragma unroll
        for (int j = 0; j < 4; j++)
#pragma unroll
            for (int r = 0; r < 4; r++) acc[i][j][r] = 0.0f;

    const int arow = tid >> 2, aq = tid & 3;
    const bool arok = (bm + arow) < M;

#define LD_AB(c, buf) do { \
        const __half* _sa = ((c) < 4) \
            ? (Am + (size_t)(bm + arow) * 256 + (c) * 64 + aq * 8) \
            : (Rt + (size_t)(bm + arow) * 256 + ((c) - 4) * 64 + aq * 8); \
        uint32_t _da = sA + (uint32_t)(buf) * 8192u; \
        uint32_t _o1 = (((uint32_t)arow * 128u + (uint32_t)aq * 16u) ^ (((uint32_t)arow & 7u) << 4)); \
        uint32_t _o2 = (((uint32_t)arow * 128u + (uint32_t)(aq + 4) * 16u) ^ (((uint32_t)arow & 7u) << 4)); \
        cp16p(_da + _o1, _sa, arok); \
        cp16p(_da + _o2, _sa + 32, arok); \
        const __half* _pb = B + (size_t)((c) * 64) * 256 + bn; \
        uint32_t _db = sB + (uint32_t)(buf) * 16384u; \
        _Pragma("unroll") \
        for (int i = 0; i < 4; i++) { \
            int row = (tid >> 4) + i * 16; \
            int seg = tid & 15; \
            uint32_t off = (((uint32_t)row * 256u + (uint32_t)seg * 16u) ^ (((uint32_t)row & 7u) << 4)); \
            cp16p(_db + off, _pb + (size_t)row * 256 + seg * 8, true); \
        } \
        CP_COMMIT(); \
    } while (0)

    LD_AB(0, 0);
    LD_AB(1, 1);

#pragma unroll
    for (int c = 0; c < 8; c++) {
        const int buf = c % 3;
        if (c + 2 < 8) {
            LD_AB(c + 2, (c + 2) % 3);
            asm volatile("cp.async.wait_group 2;" ::: "memory");
        } else if (c + 1 < 8) {
            asm volatile("cp.async.wait_group 1;" ::: "memory");
        } else {
            asm volatile("cp.async.wait_group 0;" ::: "memory");
        }
        __syncthreads();

        const uint32_t ab = sA + (uint32_t)buf * 8192u;
        const uint32_t bb = sB + (uint32_t)buf * 16384u;
#pragma unroll
        for (int ks = 0; ks < 4; ks++) {
            uint32_t a[2][4];
#pragma unroll
            for (int i = 0; i < 2; i++) {
                uint32_t mrow = (uint32_t)(m0 + i * 16 + (lane & 15));
                uint32_t kb = (uint32_t)(ks * 32 + (lane >> 4) * 16);
                uint32_t off = ((mrow * 128u + kb) ^ ((mrow & 7u) << 4));
                ldsm4(a[i][0], a[i][1], a[i][2], a[i][3], ab + off);
            }
            uint32_t bh[4][2];
#pragma unroll
            for (int j2 = 0; j2 < 2; j2++) {
                uint32_t krow = (uint32_t)(ks * 16 + (lane & 15));
                uint32_t cb = (uint32_t)((n0 + j2 * 16 + (lane >> 4) * 8) * 2);
                uint32_t off = ((krow * 256u + cb) ^ ((krow & 7u) << 4));
                ldsm4t(bh[j2 * 2][0], bh[j2 * 2][1], bh[j2 * 2 + 1][0], bh[j2 * 2 + 1][1], bb + off);
            }
#pragma unroll
            for (int i = 0; i < 2; i++)
#pragma unroll
                for (int j = 0; j < 4; j++)
                    mma16816h(acc[i][j], a[i], bh[j]);
        }
        __syncthreads();
    }

    // ---- epilogue: bias + PReLU + store (fp32 or fp16 out) ----
#pragma unroll
    for (int i = 0; i < 2; i++) {
        int r0 = bm + m0 + i * 16 + (lane >> 2);
#pragma unroll
        for (int j = 0; j < 4; j++) {
            int col = bn + n0 + j * 8 + (lane & 3) * 2;
            float2 bb = __ldg(reinterpret_cast<const float2*>(bias + col));
            float2 aa = __ldg(reinterpret_cast<const float2*>(alpha + col));
#pragma unroll
            for (int h = 0; h < 2; h++) {
                int rr = r0 + h * 8;
                if (rr >= M) continue;
                float v0 = acc[i][j][h * 2 + 0] + bb.x;
                float v1 = acc[i][j][h * 2 + 1] + bb.y;
                v0 = v0 > 0.f ? v0 : aa.x * v0;
                v1 = v1 > 0.f ? v1 : aa.y * v1;
                if (sizeof(OutT) == 4) {
                    *reinterpret_cast<float2*>((float*)out + (size_t)rr * 256 + col) = make_float2(v0, v1);
                } else {
                    uint32_t p = f2h2(v0, v1);
                    *reinterpret_cast<uint32_t*>((__half*)out + (size_t)rr * 256 + col) = p;
                }
            }
        }
    }
#undef LD_AB
}

// ---------------- launch -------------------------------------------------------
extern "C" void kernel_launch(void* const* d_in, const int* in_sizes, int n_in,
                              void* d_out, int out_size) {
    const float* x    = (const float*)d_in[0];
    const int*   src1 = (const int*)d_in[1];
    const int*   dst1 = (const int*)d_in[2];
    const int*   src2 = (const int*)d_in[3];
    const int*   dst2 = (const int*)d_in[4];

    int iW = 5;
    while (iW < n_in && in_sizes[iW] != DIN * HID) iW++;
    const float* W_l1 = (const float*)d_in[iW + 0];
    const float* W_r1 = (const float*)d_in[iW + 1];
    const float* b1   = (const float*)d_in[iW + 2];
    const float* a1   = (const float*)d_in[iW + 3];
    const float* W_l2 = (const float*)d_in[iW + 4];
    const float* W_r2 = (const float*)d_in[iW + 5];
    const float* b2   = (const float*)d_in[iW + 6];
    const float* a2   = (const float*)d_in[iW + 7];

    const int E1 = in_sizes[1];
    const int E2 = in_sizes[3];
    const int nX = in_sizes[0];

    __half *xh, *h1, *A, *B;
    int *hist, *off1, *cur1, *off2, *cur2, *ss1, *ss2;
    cudaGetSymbolAddress((void**)&xh,   g_xh);
    cudaGetSymbolAddress((void**)&h1,   g_h1);
    cudaGetSymbolAddress((void**)&A,    g_A);
    cudaGetSymbolAddress((void**)&B,    g_B);
    cudaGetSymbolAddress((void**)&hist, g_hist);
    cudaGetSymbolAddress((void**)&off1, g_off1);
    cudaGetSymbolAddress((void**)&cur1, g_cur1);
    cudaGetSymbolAddress((void**)&off2, g_off2);
    cudaGetSymbolAddress((void**)&cur2, g_cur2);
    cudaGetSymbolAddress((void**)&ss1,  g_ss1);
    cudaGetSymbolAddress((void**)&ss2,  g_ss2);

    float* out = (float*)d_out;

    const int SMEM_GEMM = 3 * 8192 + 3 * 16384;   // 72KB
    cudaFuncSetAttribute(gemm_fp16<__half>, cudaFuncAttributeMaxDynamicSharedMemorySize, SMEM_GEMM);
    cudaFuncSetAttribute(gemm_fp16<float>,  cudaFuncAttributeMaxDynamicSharedMemorySize, SMEM_GEMM);

    const int E4 = 256 * 4;
    const int hb1 = (E1 + E4 - 1) / E4;
    const int hb2 = (E2 + E4 - 1) / E4;
    const int packBlocks = (2 * 512 * 64) / 256;
    const int convBlocks = (nX + 256 * 8 - 1) / (256 * 8);

    // #1: hist1 | hist2 | B pack | x->fp16 convert, one grid
    hist_all<<<hb1 + hb2 + packBlocks + convBlocks, 256>>>(
        dst1, E1, hist, hb1, dst2, E2, hist + N1C, hb2, packBlocks,
        W_l1, W_r1, W_l2, W_r2, B, x, xh, nX);
    // #2: both scans
    scan_both<<<2, 1024>>>(hist, off1, cur1, off2, cur2);
    // #3: both reorders
    reorder_all<<<hb1 + hb2, 256>>>(src1, dst1, E1, cur1, ss1, hb1,
                                    src2, dst2, E2, cur2, ss2);
    // #4: layer-1 gather (mean only)  <-- ncu capture slot
    agg_mean_h<<<(N1C + 7) / 8, 256>>>(xh, ss1, off1, A, N1C);
    // #5: layer-1 GEMM (Rt read directly from xh)
    {
        dim3 grid(HID / FBN, (N1C + FBM - 1) / FBM);
        gemm_fp16<__half><<<grid, 256, SMEM_GEMM>>>(A, xh, B, b1, a1, h1, N1C);
    }
    // #6: layer-2 gather
    agg_mean_h<<<(N2C + 7) / 8, 256>>>(h1, ss2, off2, A, N2C);
    // #7: layer-2 GEMM (Rt read directly from h1)
    {
        dim3 grid(HID / FBN, (N2C + FBM - 1) / FBM);
        gemm_fp16<float><<<grid, 256, SMEM_GEMM>>>(A, h1, B + 512 * 256, b2, a2, out, N2C);
    }
}

// round 15
// speedup vs baseline: 1.3859x; 1.1535x over previous
#include <cuda_runtime.h>
#include <cuda_fp16.h>
#include <cstdint>

#define N1C 40000
#define N2C 8000
#define E1C 1000000
#define E2C 200000
#define DIN 256
#define HID 256
#define NXROWS 200000

// ---------------- scratch (device globals: no allocation allowed) ----------
__device__ __align__(16) __half g_xh[(size_t)NXROWS * DIN];   // fp16 copy of x (102MB)
__device__ __align__(16) __half g_h1[(size_t)N1C * HID];      // layer-1 output, fp16
__device__ __align__(16) __half g_A[(size_t)N1C * DIN];       // mean part of A only
__device__ __align__(16) __half g_B[2 * 512 * 256];           // fp16 weights
__device__ __align__(16) int g_hist[N1C + N2C];               // zero-init; scan re-zeros
__device__ int g_off1[N1C + 1];
__device__ int g_cur1[N1C];
__device__ int g_off2[N2C + 1];
__device__ int g_cur2[N2C];
__device__ int g_ss1[E1C];
__device__ int g_ss2[E2C];

// ---------------- helpers ----------------------------------------------------
__device__ __forceinline__ uint32_t smem_u32(const void* p) {
    uint32_t a;
    asm("{ .reg .u64 t; cvta.to.shared.u64 t, %1; cvt.u32.u64 %0, t; }" : "=r"(a) : "l"(p));
    return a;
}
__device__ __forceinline__ void cp16p(uint32_t dst, const void* src, bool pred) {
    int n = pred ? 16 : 0;
    asm volatile("cp.async.cg.shared.global [%0], [%1], 16, %2;" :: "r"(dst), "l"(src), "r"(n));
}
#define CP_COMMIT() asm volatile("cp.async.commit_group;" ::: "memory")
__device__ __forceinline__ void ldsm4(uint32_t& r0, uint32_t& r1, uint32_t& r2, uint32_t& r3, uint32_t a) {
    asm volatile("ldmatrix.sync.aligned.m8n8.x4.shared.b16 {%0,%1,%2,%3}, [%4];"
                 : "=r"(r0), "=r"(r1), "=r"(r2), "=r"(r3) : "r"(a));
}
__device__ __forceinline__ void ldsm4t(uint32_t& r0, uint32_t& r1, uint32_t& r2, uint32_t& r3, uint32_t a) {
    asm volatile("ldmatrix.sync.aligned.m8n8.x4.trans.shared.b16 {%0,%1,%2,%3}, [%4];"
                 : "=r"(r0), "=r"(r1), "=r"(r2), "=r"(r3) : "r"(a));
}
__device__ __forceinline__ void mma16816h(float* c, const uint32_t* a, const uint32_t* b) {
    asm volatile("mma.sync.aligned.m16n8k16.row.col.f32.f16.f16.f32 "
                 "{%0,%1,%2,%3}, {%4,%5,%6,%7}, {%8,%9}, {%0,%1,%2,%3};"
                 : "+f"(c[0]), "+f"(c[1]), "+f"(c[2]), "+f"(c[3])
                 : "r"(a[0]), "r"(a[1]), "r"(a[2]), "r"(a[3]), "r"(b[0]), "r"(b[1]));
}
__device__ __forceinline__ uint32_t f2h2(float a, float b) {
    __half2 h = __floats2half2_rn(a, b);
    return *reinterpret_cast<uint32_t*>(&h);
}
__device__ __forceinline__ void addh2(float& a, float& b, uint32_t p) {
    __half2 h = *reinterpret_cast<__half2*>(&p);
    float2 f = __half22float2(h);
    a += f.x; b += f.y;
}
__device__ __forceinline__ uint32_t hadd2u(uint32_t a, uint32_t b) {
    __half2 r = __hadd2(*reinterpret_cast<__half2*>(&a), *reinterpret_cast<__half2*>(&b));
    return *reinterpret_cast<uint32_t*>(&r);
}

// ---------------- fused front kernel: hist1 | hist2 | B pack | x convert --------
__global__ void hist_all(const int* __restrict__ dst1, int E1c, int* __restrict__ hist1, int hb1,
                         const int* __restrict__ dst2, int E2c, int* __restrict__ hist2, int hb2,
                         int packBlocks,
                         const float* __restrict__ Wl1, const float* __restrict__ Wr1,
                         const float* __restrict__ Wl2, const float* __restrict__ Wr2,
                         __half* __restrict__ B,
                         const float* __restrict__ x, __half* __restrict__ xh, int nX) {
    int bx = blockIdx.x;
    if (bx < hb1 + hb2) {
        const int* dst = (bx < hb1) ? dst1 : dst2;
        int* hist = (bx < hb1) ? hist1 : hist2;
        int E = (bx < hb1) ? E1c : E2c;
        int lb = (bx < hb1) ? bx : bx - hb1;
        int i = (lb * blockDim.x + threadIdx.x) * 4;
        if (i + 4 <= E) {
            int4 d = __ldg(reinterpret_cast<const int4*>(dst + i));
            atomicAdd(hist + d.x, 1);
            atomicAdd(hist + d.y, 1);
            atomicAdd(hist + d.z, 1);
            atomicAdd(hist + d.w, 1);
        } else {
            for (int j = i; j < E; j++) atomicAdd(hist + __ldg(dst + j), 1);
        }
    } else if (bx < hb1 + hb2 + packBlocks) {
        int idx = (bx - hb1 - hb2) * blockDim.x + threadIdx.x;  // < 2*512*64
        int l = idx >> 15;
        int k = (idx >> 6) & 511;
        int col = (idx & 63) * 4;
        const float* W = (l == 0) ? ((k < 256) ? Wl1 : Wr1) : ((k < 256) ? Wl2 : Wr2);
        float4 v = __ldg(reinterpret_cast<const float4*>(W + (size_t)(k & 255) * 256 + col));
        size_t o = ((size_t)l * 512 + k) * 256 + col;
        *reinterpret_cast<uint2*>(B + o) = make_uint2(f2h2(v.x, v.y), f2h2(v.z, v.w));
    } else {
        size_t base = ((size_t)(bx - hb1 - hb2 - packBlocks) * blockDim.x + threadIdx.x) * 8;
        if (base + 8 <= (size_t)nX) {
            float4 v0 = __ldg(reinterpret_cast<const float4*>(x + base));
            float4 v1 = __ldg(reinterpret_cast<const float4*>(x + base + 4));
            uint4 o;
            o.x = f2h2(v0.x, v0.y); o.y = f2h2(v0.z, v0.w);
            o.z = f2h2(v1.x, v1.y); o.w = f2h2(v1.z, v1.w);
            *reinterpret_cast<uint4*>(xh + base) = o;
        }
    }
}

// ---------------- coalesced tiled scan (warp-shuffle), re-zeros hist ----------
__device__ void scan_dev(int* __restrict__ hist, int n,
                         int* __restrict__ off, int* __restrict__ cur) {
    __shared__ int wsum[32];
    __shared__ int carry;
    int t = threadIdx.x;
    int lane = t & 31, wid = t >> 5;
    if (t == 0) carry = 0;
    __syncthreads();
    for (int base = 0; base < n; base += 1024) {
        int idx = base + t;
        int v = (idx < n) ? hist[idx] : 0;
        // warp inclusive scan
        int vs = v;
#pragma unroll
        for (int d = 1; d < 32; d <<= 1) {
            int u = __shfl_up_sync(0xFFFFFFFF, vs, d);
            if (lane >= d) vs += u;
        }
        if (lane == 31) wsum[wid] = vs;
        __syncthreads();
        if (wid == 0) {
            int w = wsum[lane];
#pragma unroll
            for (int d = 1; d < 32; d <<= 1) {
                int u = __shfl_up_sync(0xFFFFFFFF, w, d);
                if (lane >= d) w += u;
            }
            wsum[lane] = w;
        }
        __syncthreads();
        int winc = (wid > 0) ? wsum[wid - 1] : 0;
        int exc = vs - v + winc + carry;
        if (idx < n) {
            off[idx] = exc;
            cur[idx] = exc;
            hist[idx] = 0;
        }
        __syncthreads();
        if (t == 0) carry += wsum[31];
        __syncthreads();
    }
    if (t == 0) off[n] = carry;
}

__global__ void scan_both(int* __restrict__ hist,
                          int* __restrict__ off1, int* __restrict__ cur1,
                          int* __restrict__ off2, int* __restrict__ cur2) {
    if (blockIdx.x == 0) scan_dev(hist, N1C, off1, cur1);
    else                 scan_dev(hist + N1C, N2C, off2, cur2);
}

// ---------------- reorder both layers, grid-partitioned -------------------------
__device__ __forceinline__ void reorder_dev(const int* __restrict__ src, const int* __restrict__ dst,
                                            int E, int* __restrict__ cur, int* __restrict__ ssrc,
                                            int lb) {
    int i = (lb * (int)blockDim.x + (int)threadIdx.x) * 4;
    if (i + 4 <= E) {
        int4 d = __ldg(reinterpret_cast<const int4*>(dst + i));
        int4 s = __ldg(reinterpret_cast<const int4*>(src + i));
        int p0 = atomicAdd(cur + d.x, 1);
        int p1 = atomicAdd(cur + d.y, 1);
        int p2 = atomicAdd(cur + d.z, 1);
        int p3 = atomicAdd(cur + d.w, 1);
        ssrc[p0] = s.x; ssrc[p1] = s.y; ssrc[p2] = s.z; ssrc[p3] = s.w;
    } else {
        for (int j = i; j < E; j++) {
            int pos = atomicAdd(cur + __ldg(dst + j), 1);
            ssrc[pos] = __ldg(src + j);
        }
    }
}

__global__ void reorder_all(const int* __restrict__ src1, const int* __restrict__ dst1, int E1c,
                            int* __restrict__ cur1, int* __restrict__ ss1, int rb1,
                            const int* __restrict__ src2, const int* __restrict__ dst2, int E2c,
                            int* __restrict__ cur2, int* __restrict__ ss2) {
    int bx = blockIdx.x;
    if (bx < rb1) reorder_dev(src1, dst1, E1c, cur1, ss1, bx);
    else          reorder_dev(src2, dst2, E2c, cur2, ss2, bx - rb1);
}

// ---------------- segmented gather-mean (pairwise hadd2 pre-add) ---------------
__global__ __launch_bounds__(256)
void agg_mean_h(const __half* __restrict__ xh,
                const int* __restrict__ ssrc, const int* __restrict__ off,
                __half* __restrict__ A, int n_tgt) {
    int w = (blockIdx.x * blockDim.x + threadIdx.x) >> 5;
    if (w >= n_tgt) return;
    int lane = threadIdx.x & 31;
    int s0 = __ldg(off + w), s1 = __ldg(off + w + 1);

    float a0 = 0.f, a1 = 0.f, a2 = 0.f, a3 = 0.f, a4 = 0.f, a5 = 0.f, a6 = 0.f, a7 = 0.f;
    int e = s0;
    for (; e + 8 <= s1; e += 8) {
        int si[8];
#pragma unroll
        for (int j = 0; j < 8; j++) si[j] = __ldg(ssrc + e + j);
        uint4 v[8];
#pragma unroll
        for (int j = 0; j < 8; j++)
            v[j] = __ldg(reinterpret_cast<const uint4*>(xh + (size_t)si[j] * 256) + lane);
        // pairwise fp16 pre-add (one rounding per pair), then fp32 accumulate
#pragma unroll
        for (int j = 0; j < 8; j += 2) {
            uint32_t px = hadd2u(v[j].x, v[j + 1].x);
            uint32_t py = hadd2u(v[j].y, v[j + 1].y);
            uint32_t pz = hadd2u(v[j].z, v[j + 1].z);
            uint32_t pw = hadd2u(v[j].w, v[j + 1].w);
            addh2(a0, a1, px);
            addh2(a2, a3, py);
            addh2(a4, a5, pz);
            addh2(a6, a7, pw);
        }
    }
    for (; e < s1; e++) {
        int si = __ldg(ssrc + e);
        uint4 v = __ldg(reinterpret_cast<const uint4*>(xh + (size_t)si * 256) + lane);
        addh2(a0, a1, v.x);
        addh2(a2, a3, v.y);
        addh2(a4, a5, v.z);
        addh2(a6, a7, v.w);
    }
    float inv = 1.0f / fmaxf((float)(s1 - s0), 1.0f);
    uint4 om;
    om.x = f2h2(a0 * inv, a1 * inv);
    om.y = f2h2(a2 * inv, a3 * inv);
    om.z = f2h2(a4 * inv, a5 * inv);
    om.w = f2h2(a6 * inv, a7 * inv);

    *(reinterpret_cast<uint4*>(A + (size_t)w * 256) + lane) = om;
}

// ---------------- fp16 GEMM: A = [mean | root(direct)], 3 CTAs/SM --------------
#define FBM 64
#define FBN 128

template <typename OutT>
__global__ __launch_bounds__(256, 3)
void gemm_fp16(const __half* __restrict__ Am, const __half* __restrict__ Rt,
               const __half* __restrict__ B,
               const float* __restrict__ bias, const float* __restrict__ alpha,
               OutT* __restrict__ out, int M) {
    extern __shared__ char smem[];
    uint32_t sb = smem_u32(smem);
    const uint32_t sA = sb;              // 3 x 8KB
    const uint32_t sB = sb + 24576u;     // 3 x 16KB
    const int tid = threadIdx.x;
    const int wid = tid >> 5, lane = tid & 31;
    const int bm = blockIdx.y * FBM;
    const int bn = blockIdx.x * FBN;
    const int m0 = (wid & 1) * 32;
    const int n0 = (wid >> 1) * 32;

    float acc[2][4][4];
#pragma unroll
    for (int i = 0; i < 2; i++)
#pragma unroll
        for (int j = 0; j < 4; j++)
#pragma unroll
            for (int r = 0; r < 4; r++) acc[i][j][r] = 0.0f;

    const int arow = tid >> 2, aq = tid & 3;
    const bool arok = (bm + arow) < M;

#define LD_AB(c, buf) do { \
        const __half* _sa = ((c) < 4) \
            ? (Am + (size_t)(bm + arow) * 256 + (c) * 64 + aq * 8) \
            : (Rt + (size_t)(bm + arow) * 256 + ((c) - 4) * 64 + aq * 8); \
        uint32_t _da = sA + (uint32_t)(buf) * 8192u; \
        uint32_t _o1 = (((uint32_t)arow * 128u + (uint32_t)aq * 16u) ^ (((uint32_t)arow & 7u) << 4)); \
        uint32_t _o2 = (((uint32_t)arow * 128u + (uint32_t)(aq + 4) * 16u) ^ (((uint32_t)arow & 7u) << 4)); \
        cp16p(_da + _o1, _sa, arok); \
        cp16p(_da + _o2, _sa + 32, arok); \
        const __half* _pb = B + (size_t)((c) * 64) * 256 + bn; \
        uint32_t _db = sB + (uint32_t)(buf) * 16384u; \
        _Pragma("unroll") \
        for (int i = 0; i < 4; i++) { \
            int row = (tid >> 4) + i * 16; \
            int seg = tid & 15; \
            uint32_t off = (((uint32_t)row * 256u + (uint32_t)seg * 16u) ^ (((uint32_t)row & 7u) << 4)); \
            cp16p(_db + off, _pb + (size_t)row * 256 + seg * 8, true); \
        } \
        CP_COMMIT(); \
    } while (0)

    LD_AB(0, 0);
    LD_AB(1, 1);

#pragma unroll
    for (int c = 0; c < 8; c++) {
        const int buf = c % 3;
        if (c + 2 < 8) {
            LD_AB(c + 2, (c + 2) % 3);
            asm volatile("cp.async.wait_group 2;" ::: "memory");
        } else if (c + 1 < 8) {
            asm volatile("cp.async.wait_group 1;" ::: "memory");
        } else {
            asm volatile("cp.async.wait_group 0;" ::: "memory");
        }
        __syncthreads();

        const uint32_t ab = sA + (uint32_t)buf * 8192u;
        const uint32_t bb = sB + (uint32_t)buf * 16384u;
#pragma unroll
        for (int ks = 0; ks < 4; ks++) {
            uint32_t a[2][4];
#pragma unroll
            for (int i = 0; i < 2; i++) {
                uint32_t mrow = (uint32_t)(m0 + i * 16 + (lane & 15));
                uint32_t kb = (uint32_t)(ks * 32 + (lane >> 4) * 16);
                uint32_t off = ((mrow * 128u + kb) ^ ((mrow & 7u) << 4));
                ldsm4(a[i][0], a[i][1], a[i][2], a[i][3], ab + off);
            }
            uint32_t bh[4][2];
#pragma unroll
            for (int j2 = 0; j2 < 2; j2++) {
                uint32_t krow = (uint32_t)(ks * 16 + (lane & 15));
                uint32_t cb = (uint32_t)((n0 + j2 * 16 + (lane >> 4) * 8) * 2);
                uint32_t off = ((krow * 256u + cb) ^ ((krow & 7u) << 4));
                ldsm4t(bh[j2 * 2][0], bh[j2 * 2][1], bh[j2 * 2 + 1][0], bh[j2 * 2 + 1][1], bb + off);
            }
#pragma unroll
            for (int i = 0; i < 2; i++)
#pragma unroll
                for (int j = 0; j < 4; j++)
                    mma16816h(acc[i][j], a[i], bh[j]);
        }
        __syncthreads();
    }

    // ---- epilogue: bias + PReLU + store (fp32 or fp16 out) ----
#pragma unroll
    for (int i = 0; i < 2; i++) {
        int r0 = bm + m0 + i * 16 + (lane >> 2);
#pragma unroll
        for (int j = 0; j < 4; j++) {
            int col = bn + n0 + j * 8 + (lane & 3) * 2;
            float2 bb = __ldg(reinterpret_cast<const float2*>(bias + col));
            float2 aa = __ldg(reinterpret_cast<const float2*>(alpha + col));
#pragma unroll
            for (int h = 0; h < 2; h++) {
                int rr = r0 + h * 8;
                if (rr >= M) continue;
                float v0 = acc[i][j][h * 2 + 0] + bb.x;
                float v1 = acc[i][j][h * 2 + 1] + bb.y;
                v0 = v0 > 0.f ? v0 : aa.x * v0;
                v1 = v1 > 0.f ? v1 : aa.y * v1;
                if (sizeof(OutT) == 4) {
                    *reinterpret_cast<float2*>((float*)out + (size_t)rr * 256 + col) = make_float2(v0, v1);
                } else {
                    uint32_t p = f2h2(v0, v1);
                    *reinterpret_cast<uint32_t*>((__half*)out + (size_t)rr * 256 + col) = p;
                }
            }
        }
    }
#undef LD_AB
}

// ---------------- launch -------------------------------------------------------
extern "C" void kernel_launch(void* const* d_in, const int* in_sizes, int n_in,
                              void* d_out, int out_size) {
    const float* x    = (const float*)d_in[0];
    const int*   src1 = (const int*)d_in[1];
    const int*   dst1 = (const int*)d_in[2];
    const int*   src2 = (const int*)d_in[3];
    const int*   dst2 = (const int*)d_in[4];

    int iW = 5;
    while (iW < n_in && in_sizes[iW] != DIN * HID) iW++;
    const float* W_l1 = (const float*)d_in[iW + 0];
    const float* W_r1 = (const float*)d_in[iW + 1];
    const float* b1   = (const float*)d_in[iW + 2];
    const float* a1   = (const float*)d_in[iW + 3];
    const float* W_l2 = (const float*)d_in[iW + 4];
    const float* W_r2 = (const float*)d_in[iW + 5];
    const float* b2   = (const float*)d_in[iW + 6];
    const float* a2   = (const float*)d_in[iW + 7];

    const int E1 = in_sizes[1];
    const int E2 = in_sizes[3];
    const int nX = in_sizes[0];

    __half *xh, *h1, *A, *B;
    int *hist, *off1, *cur1, *off2, *cur2, *ss1, *ss2;
    cudaGetSymbolAddress((void**)&xh,   g_xh);
    cudaGetSymbolAddress((void**)&h1,   g_h1);
    cudaGetSymbolAddress((void**)&A,    g_A);
    cudaGetSymbolAddress((void**)&B,    g_B);
    cudaGetSymbolAddress((void**)&hist, g_hist);
    cudaGetSymbolAddress((void**)&off1, g_off1);
    cudaGetSymbolAddress((void**)&cur1, g_cur1);
    cudaGetSymbolAddress((void**)&off2, g_off2);
    cudaGetSymbolAddress((void**)&cur2, g_cur2);
    cudaGetSymbolAddress((void**)&ss1,  g_ss1);
    cudaGetSymbolAddress((void**)&ss2,  g_ss2);

    float* out = (float*)d_out;

    const int SMEM_GEMM = 3 * 8192 + 3 * 16384;   // 72KB
    cudaFuncSetAttribute(gemm_fp16<__half>, cudaFuncAttributeMaxDynamicSharedMemorySize, SMEM_GEMM);
    cudaFuncSetAttribute(gemm_fp16<float>,  cudaFuncAttributeMaxDynamicSharedMemorySize, SMEM_GEMM);

    const int E4 = 256 * 4;
    const int hb1 = (E1 + E4 - 1) / E4;
    const int hb2 = (E2 + E4 - 1) / E4;
    const int packBlocks = (2 * 512 * 64) / 256;
    const int convBlocks = (nX + 256 * 8 - 1) / (256 * 8);

    // #1: hist1 | hist2 | B pack | x->fp16 convert, one grid
    hist_all<<<hb1 + hb2 + packBlocks + convBlocks, 256>>>(
        dst1, E1, hist, hb1, dst2, E2, hist + N1C, hb2, packBlocks,
        W_l1, W_r1, W_l2, W_r2, B, x, xh, nX);
    // #2: both scans (warp-shuffle tiled)
    scan_both<<<2, 1024>>>(hist, off1, cur1, off2, cur2);
    // #3: both reorders
    reorder_all<<<hb1 + hb2, 256>>>(src1, dst1, E1, cur1, ss1, hb1,
                                    src2, dst2, E2, cur2, ss2);
    // #4: layer-1 gather (mean only)  <-- ncu capture slot
    agg_mean_h<<<(N1C + 7) / 8, 256>>>(xh, ss1, off1, A, N1C);
    // #5: layer-1 GEMM (Rt read directly from xh)
    {
        dim3 grid(HID / FBN, (N1C + FBM - 1) / FBM);
        gemm_fp16<__half><<<grid, 256, SMEM_GEMM>>>(A, xh, B, b1, a1, h1, N1C);
    }
    // #6: layer-2 gather
    agg_mean_h<<<(N2C + 7) / 8, 256>>>(h1, ss2, off2, A, N2C);
    // #7: layer-2 GEMM (Rt read directly from h1)
    {
        dim3 grid(HID / FBN, (N2C + FBM - 1) / FBM);
        gemm_fp16<float><<<grid, 256, SMEM_GEMM>>>(A, h1, B + 512 * 256, b2, a2, out, N2C);
    }
}